// round 7
// baseline (speedup 1.0000x reference)
#include <cuda_runtime.h>
#include <math.h>

#define BB 256
#define SS 512
#define EE 128
#define HH 256
#define NCOL 8
#define NJT 16
#define BT 32
#define HSP 260

typedef unsigned long long ull;

// device scratch (no allocations allowed)
__device__ float g_enc_out[BB * SS * HH];   // encoder hidden states (h feed for enc phase)
__device__ float g_hbuf[2 * BB * HH];       // process-block h ping-pong
__device__ float g_M[1024 * 2];             // enc_Wih @ W_emb
__device__ float g_bias[1024];              // enc_bih + enc_bhh
__device__ float g_xp[1024];                // pb_Wih @ dec_input + pb biases
__device__ float g_q[BB * HH];
__device__ float g_u[BB * SS];
__device__ int   g_flag[NCOL * 1024 * NJT]; // per (col, step, producer) done flags

__device__ __forceinline__ ull f2u(float a, float b) {
    ull r; asm("mov.b64 %0,{%1,%2};" : "=l"(r) : "f"(a), "f"(b)); return r;
}
__device__ __forceinline__ float2 u2f(ull v) {
    float2 r; asm("mov.b64 {%0,%1},%2;" : "=f"(r.x), "=f"(r.y) : "l"(v)); return r;
}
__device__ __forceinline__ ull ffma2(ull a, ull b, ull c) {
    ull d; asm("fma.rn.f32x2 %0,%1,%2,%3;" : "=l"(d) : "l"(a), "l"(b), "l"(c)); return d;
}
__device__ __forceinline__ float fsig(float x) {
    return __fdividef(1.f, 1.f + __expf(-x));
}
__device__ __forceinline__ float ftanh(float x) {
    x = fminf(fmaxf(x, -10.f), 10.f);
    float e = __expf(2.f * x);
    return __fdividef(e - 1.f, e + 1.f);
}

// ------------------- init: fold small matrices, zero flags -------------------
__global__ void init_kernel(const float* __restrict__ encWih, const float* __restrict__ Wemb,
                            const float* __restrict__ encBih, const float* __restrict__ encBhh,
                            const float* __restrict__ pbWih,  const float* __restrict__ decIn,
                            const float* __restrict__ pbBih,  const float* __restrict__ pbBhh)
{
    int r = blockIdx.x * blockDim.x + threadIdx.x;
    if (r >= 1024) return;
    float m0 = 0.f, m1 = 0.f, xp = 0.f;
    for (int e = 0; e < EE; e++) {
        float w = encWih[r * EE + e];
        m0 = fmaf(w, Wemb[e * 2 + 0], m0);
        m1 = fmaf(w, Wemb[e * 2 + 1], m1);
        xp = fmaf(pbWih[r * EE + e], decIn[e], xp);
    }
    g_M[2 * r] = m0; g_M[2 * r + 1] = m1;
    g_bias[r] = encBih[r] + encBhh[r];
    g_xp[r]   = xp + pbBih[r] + pbBhh[r];
#pragma unroll
    for (int q = 0; q < 128; q++) g_flag[r * 128 + q] = 0;
}

// Load 64-row weight slice packed over k-pairs: ws[kp*64 + r] = (W[grow][2kp], W[grow][2kp+1])
// gatemap: position r = m*16+jg holds W row m*HH + j0 + jg (gate-aligned for LSTM)
// else:    position r holds W row j0 + r (straight, for attention)
__device__ __forceinline__ void load_wp(ull* ws, const float* __restrict__ W, int j0,
                                        int tid, bool gatemap)
{
    int r = tid >> 2;                       // 0..63 storage position
    int grow = gatemap ? ((r >> 4) * HH + j0 + (r & 15)) : (j0 + r);
    int kbase = (tid & 3) << 6;             // 0,64,128,192
    const float4* src = (const float4*)(W + (size_t)grow * HH + kbase);
#pragma unroll
    for (int q = 0; q < 16; q++) {
        float4 v = src[q];
        int kp = (kbase >> 1) + q * 2;
        ws[(size_t)kp * 64 + r]       = f2u(v.x, v.y);
        ws[(size_t)(kp + 1) * 64 + r] = f2u(v.z, v.w);
    }
}

// ------------------- persistent LSTM: encoder then process block -------------------
__global__ void __launch_bounds__(256, 1)
lstm_kernel(const float* __restrict__ inp,
            const float* __restrict__ encWhh,
            const float* __restrict__ pbWhh)
{
    extern __shared__ ull smu[];
    ull*   ws = smu;                        // [128 kp][64 rows]
    float* hs = (float*)(smu + 128 * 64);   // [32][HSP]

    const int tid = threadIdx.x;
    const int col = blockIdx.x & 7;
    const int jt  = blockIdx.x >> 3;
    const int b0g = col * BT;
    const int j0  = jt * 16;
    const int jg  = tid & 15;
    const int bg  = tid >> 4;
    const int bb  = bg * 2;
    const int b_ld = tid >> 6;              // h-fill base row
    const int kq   = (tid & 63) << 2;       // h-fill k offset

    // per-thread step-invariant constants (4 gates of hidden dim j0+jg)
    float cex[4], cey[4], ceb[4], cxp[4];
#pragma unroll
    for (int m = 0; m < 4; m++) {
        int grow = m * HH + j0 + jg;
        cex[m] = g_M[2 * grow]; cey[m] = g_M[2 * grow + 1];
        ceb[m] = g_bias[grow];  cxp[m] = g_xp[grow];
    }
    load_wp(ws, encWhh, j0, tid, true);
    __syncthreads();

    float c0 = 0.f, c1 = 0.f;

    for (int step = 0; step < 1024; step++) {
        const bool enc = step < 512;
        if (step == 512) load_wp(ws, pbWhh, j0, tid, true);   // mid-step sync protects

        if (step >= 1) {
            // poll all 16 producer flags of step-1 (every thread; broadcast line)
            const int* fb = g_flag + ((size_t)((col << 10) + (step - 1))) * NJT;
            for (;;) {
                int a0, a1, a2, a3, b0, b1, b2, b3;
                asm volatile("ld.acquire.gpu.global.v4.b32 {%0,%1,%2,%3},[%4];"
                             : "=r"(a0), "=r"(a1), "=r"(a2), "=r"(a3) : "l"(fb) : "memory");
                asm volatile("ld.acquire.gpu.global.v4.b32 {%0,%1,%2,%3},[%4];"
                             : "=r"(b0), "=r"(b1), "=r"(b2), "=r"(b3) : "l"(fb + 4) : "memory");
                int c2, c3, c4, c5, d0, d1, d2, d3;
                asm volatile("ld.acquire.gpu.global.v4.b32 {%0,%1,%2,%3},[%4];"
                             : "=r"(c2), "=r"(c3), "=r"(c4), "=r"(c5) : "l"(fb + 8) : "memory");
                asm volatile("ld.acquire.gpu.global.v4.b32 {%0,%1,%2,%3},[%4];"
                             : "=r"(d0), "=r"(d1), "=r"(d2), "=r"(d3) : "l"(fb + 12) : "memory");
                if ((a0 & a1 & a2 & a3 & b0 & b1 & b2 & b3 &
                     c2 & c3 & c4 & c5 & d0 & d1 & d2 & d3) != 0) break;
                __nanosleep(20);
            }
            // fill hs (32 x 256) from the column's published h
            float4 tv[8];
#pragma unroll
            for (int it = 0; it < 8; it++) {
                int b = b_ld + it * 4;
                const float* src = (step <= 512)
                    ? (g_enc_out + ((size_t)(b0g + b) * SS + (step - 1)) * HH + kq)
                    : (g_hbuf + (size_t)((step - 513) & 1) * BB * HH + (size_t)(b0g + b) * HH + kq);
                tv[it] = __ldcg((const float4*)src);
            }
#pragma unroll
            for (int it = 0; it < 8; it++)
                *(float4*)(hs + (b_ld + it * 4) * HSP + kq) = tv[it];
        }
        __syncthreads();

        // x inputs (issued early, consumed after GEMM)
        float2 x0 = make_float2(0.f, 0.f), x1 = make_float2(0.f, 0.f);
        if (enc) {
            x0 = __ldg((const float2*)(inp + ((size_t)(b0g + bb)     * SS + step) * 2));
            x1 = __ldg((const float2*)(inp + ((size_t)(b0g + bb + 1) * SS + step) * 2));
        }

        // packed GEMM: 2 batches x 4 gate-rows, k packed in pairs
        ull acc0[4] = {0, 0, 0, 0}, acc1[4] = {0, 0, 0, 0};
        if (step >= 1) {
            const float* hp0 = hs + bb * HSP;
            const float* hp1 = hp0 + HSP;
#pragma unroll 8
            for (int k = 0; k < HH; k += 4) {
                ulonglong2 H0 = *(const ulonglong2*)(hp0 + k);
                ulonglong2 H1 = *(const ulonglong2*)(hp1 + k);
                const ull* wp = ws + (size_t)(k >> 1) * 64 + jg;
#pragma unroll
                for (int m = 0; m < 4; m++) {
                    ull wa = wp[m * 16];
                    ull wb = wp[64 + m * 16];
                    acc0[m] = ffma2(H0.x, wa, acc0[m]);
                    acc0[m] = ffma2(H0.y, wb, acc0[m]);
                    acc1[m] = ffma2(H1.x, wa, acc1[m]);
                    acc1[m] = ffma2(H1.y, wb, acc1[m]);
                }
            }
        }
        float g0[4], g1[4];
#pragma unroll
        for (int m = 0; m < 4; m++) {
            float2 p = u2f(acc0[m]); g0[m] = p.x + p.y;
            float2 q = u2f(acc1[m]); g1[m] = q.x + q.y;
            if (enc) {
                g0[m] += fmaf(cex[m], x0.x, fmaf(cey[m], x0.y, ceb[m]));
                g1[m] += fmaf(cex[m], x1.x, fmaf(cey[m], x1.y, ceb[m]));
            } else {
                g0[m] += cxp[m];
                g1[m] += cxp[m];
            }
        }
        c0 = fsig(g0[1]) * c0 + fsig(g0[0]) * ftanh(g0[2]);
        float h0 = fsig(g0[3]) * ftanh(c0);
        c1 = fsig(g1[1]) * c1 + fsig(g1[0]) * ftanh(g1[2]);
        float h1 = fsig(g1[3]) * ftanh(c1);

        if (enc) {
            g_enc_out[((size_t)(b0g + bb)     * SS + step) * HH + j0 + jg] = h0;
            g_enc_out[((size_t)(b0g + bb + 1) * SS + step) * HH + j0 + jg] = h1;
        } else {
            size_t base = (size_t)((step - 512) & 1) * BB * HH;
            g_hbuf[base + (size_t)(b0g + bb)     * HH + j0 + jg] = h0;
            g_hbuf[base + (size_t)(b0g + bb + 1) * HH + j0 + jg] = h1;
        }
        __syncthreads();
        if (tid == 0) {
            __threadfence();
            asm volatile("st.release.gpu.global.b32 [%0], %1;"
                         :: "l"(g_flag + ((size_t)((col << 10) + step)) * NJT + jt), "r"(1)
                         : "memory");
        }
    }
}

// ------------------- q = h_final @ Wq^T + bq -------------------
__global__ void qproj_kernel(const float* __restrict__ Wq, const float* __restrict__ bq)
{
    __shared__ float hb[HH];
    int b = blockIdx.x, j = threadIdx.x;
    hb[j] = g_hbuf[(size_t)BB * HH + (size_t)b * HH + j];   // final pb h is in slot 1
    __syncthreads();
    float a = bq[j];
    const float* w = Wq + (size_t)j * HH;
#pragma unroll 8
    for (int k = 0; k < HH; k++) a = fmaf(hb[k], w[k], a);
    g_q[(size_t)b * HH + j] = a;
}

// ------------------- u[b,s] = sum_j V[j] * tanh(enc@Wref^T + bref + q) -------------------
__global__ void __launch_bounds__(256, 2)
attnU_kernel(const float* __restrict__ Wref, const float* __restrict__ bref,
             const float* __restrict__ V)
{
    extern __shared__ ull smu[];
    ull*   wt = smu;                        // [128 kp][64 rows]
    float* es = (float*)(smu + 128 * 64);   // [32][HSP]
    float* us = es + 32 * HSP;              // [32][17]

    const int tid = threadIdx.x;
    const int b  = blockIdx.y;
    const int s0 = blockIdx.x * 32;
    const int jg = tid & 15;
    const int bg = tid >> 4;
    const int sn = bg * 2;
    const int b_ld = tid >> 6;
    const int kq   = (tid & 63) << 2;

#pragma unroll
    for (int it = 0; it < 8; it++) {
        int s = b_ld + it * 4;
        *(float4*)(es + s * HSP + kq) =
            __ldcg((const float4*)(g_enc_out + ((size_t)b * SS + s0 + s) * HH + kq));
    }

    float u0 = 0.f, u1 = 0.f;
    for (int jt = 0; jt < 4; jt++) {
        __syncthreads();
        load_wp(wt, Wref, jt * 64, tid, false);
        __syncthreads();

        ull acc0[4] = {0, 0, 0, 0}, acc1[4] = {0, 0, 0, 0};
        const float* hp0 = es + sn * HSP;
        const float* hp1 = hp0 + HSP;
#pragma unroll 8
        for (int k = 0; k < HH; k += 4) {
            ulonglong2 H0 = *(const ulonglong2*)(hp0 + k);
            ulonglong2 H1 = *(const ulonglong2*)(hp1 + k);
            const ull* wp = wt + (size_t)(k >> 1) * 64 + jg;
#pragma unroll
            for (int m = 0; m < 4; m++) {
                ull wa = wp[m * 16];
                ull wb = wp[64 + m * 16];
                acc0[m] = ffma2(H0.x, wa, acc0[m]);
                acc0[m] = ffma2(H0.y, wb, acc0[m]);
                acc1[m] = ffma2(H1.x, wa, acc1[m]);
                acc1[m] = ffma2(H1.y, wb, acc1[m]);
            }
        }
#pragma unroll
        for (int m = 0; m < 4; m++) {
            int j = jt * 64 + m * 16 + jg;
            float2 p = u2f(acc0[m]); float v0 = p.x + p.y;
            float2 q = u2f(acc1[m]); float v1 = q.x + q.y;
            float addv = __ldg(bref + j) + g_q[(size_t)b * HH + j];
            float vv = __ldg(V + j);
            u0 += ftanh(v0 + addv) * vv;
            u1 += ftanh(v1 + addv) * vv;
        }
    }
    us[sn * 17 + jg]       = u0;
    us[(sn + 1) * 17 + jg] = u1;
    __syncthreads();
    if (tid < 32) {
        float t = 0.f;
#pragma unroll
        for (int q = 0; q < 16; q++) t += us[tid * 17 + q];
        g_u[(size_t)b * SS + s0 + tid] = t;
    }
}

// ------------------- softmax + glimpse + head -------------------
__global__ void final_kernel(const float* __restrict__ Wd1, const float* __restrict__ Wd2,
                             float* __restrict__ out)
{
    __shared__ float al[SS];
    __shared__ float red[8];
    __shared__ float gb[HH];
    int b = blockIdx.x, tid = threadIdx.x;
    int lane = tid & 31, wid = tid >> 5;

    float u0 = g_u[(size_t)b * SS + tid];
    float u1 = g_u[(size_t)b * SS + 256 + tid];

    float m = fmaxf(u0, u1);
#pragma unroll
    for (int o = 16; o > 0; o >>= 1) m = fmaxf(m, __shfl_xor_sync(0xffffffffu, m, o));
    if (lane == 0) red[wid] = m;
    __syncthreads();
    float M2 = red[0];
#pragma unroll
    for (int w = 1; w < 8; w++) M2 = fmaxf(M2, red[w]);
    __syncthreads();

    float e0 = __expf(u0 - M2), e1 = __expf(u1 - M2);
    al[tid] = e0; al[tid + 256] = e1;
    float s = e0 + e1;
#pragma unroll
    for (int o = 16; o > 0; o >>= 1) s += __shfl_xor_sync(0xffffffffu, s, o);
    if (lane == 0) red[wid] = s;
    __syncthreads();
    float Ssum = 0.f;
#pragma unroll
    for (int w = 0; w < 8; w++) Ssum += red[w];
    __syncthreads();

    float a0 = 0.f, a1 = 0.f, a2 = 0.f, a3 = 0.f;
    const float* ep = g_enc_out + (size_t)b * SS * HH + tid;
    for (int sIdx = 0; sIdx < SS; sIdx += 4) {
        a0 = fmaf(al[sIdx + 0], __ldcg(ep + (size_t)(sIdx + 0) * HH), a0);
        a1 = fmaf(al[sIdx + 1], __ldcg(ep + (size_t)(sIdx + 1) * HH), a1);
        a2 = fmaf(al[sIdx + 2], __ldcg(ep + (size_t)(sIdx + 2) * HH), a2);
        a3 = fmaf(al[sIdx + 3], __ldcg(ep + (size_t)(sIdx + 3) * HH), a3);
    }
    gb[tid] = ((a0 + a1) + (a2 + a3)) / Ssum;
    __syncthreads();

    float t = 0.f;
    const float* w1 = Wd1 + (size_t)tid * HH;
#pragma unroll 8
    for (int k = 0; k < HH; k++) t = fmaf(gb[k], w1[k], t);
    t = fmaxf(t, 0.f) * __ldg(Wd2 + tid);
#pragma unroll
    for (int o = 16; o > 0; o >>= 1) t += __shfl_xor_sync(0xffffffffu, t, o);
    if (lane == 0) red[wid] = t;
    __syncthreads();
    if (tid == 0) {
        float r = 0.f;
#pragma unroll
        for (int w = 0; w < 8; w++) r += red[w];
        out[b] = r;
    }
}

extern "C" void kernel_launch(void* const* d_in, const int* in_sizes, int n_in,
                              void* d_out, int out_size)
{
    const float* inp    = (const float*)d_in[0];
    const float* Wemb   = (const float*)d_in[1];
    const float* decIn  = (const float*)d_in[2];
    const float* encWih = (const float*)d_in[3];
    const float* encWhh = (const float*)d_in[4];
    const float* encBih = (const float*)d_in[5];
    const float* encBhh = (const float*)d_in[6];
    const float* pbWih  = (const float*)d_in[7];
    const float* pbWhh  = (const float*)d_in[8];
    const float* pbBih  = (const float*)d_in[9];
    const float* pbBhh  = (const float*)d_in[10];
    const float* Wq     = (const float*)d_in[11];
    const float* bq     = (const float*)d_in[12];
    const float* Wref   = (const float*)d_in[13];
    const float* bref   = (const float*)d_in[14];
    const float* V      = (const float*)d_in[15];
    const float* Wd1    = (const float*)d_in[16];
    const float* Wd2    = (const float*)d_in[17];

    const int LSTM_SMEM = 128 * 64 * 8 + 32 * HSP * 4;                 // 98816
    const int ATTN_SMEM = 128 * 64 * 8 + 32 * HSP * 4 + 32 * 17 * 4;   // 100992

    cudaFuncSetAttribute(lstm_kernel,  cudaFuncAttributeMaxDynamicSharedMemorySize, LSTM_SMEM);
    cudaFuncSetAttribute(attnU_kernel, cudaFuncAttributeMaxDynamicSharedMemorySize, ATTN_SMEM);

    init_kernel<<<4, 256>>>(encWih, Wemb, encBih, encBhh, pbWih, decIn, pbBih, pbBhh);
    lstm_kernel<<<NCOL * NJT, 256, LSTM_SMEM>>>(inp, encWhh, pbWhh);
    qproj_kernel<<<BB, 256>>>(Wq, bq);
    attnU_kernel<<<dim3(SS / 32, BB), 256, ATTN_SMEM>>>(Wref, bref, V);
    final_kernel<<<BB, 256>>>(Wd1, Wd2, (float*)d_out);
}

// round 9
// speedup vs baseline: 1.9539x; 1.9539x over previous
#include <cuda_runtime.h>
#include <cuda_bf16.h>
#include <math.h>

#define BB 256
#define SS 512
#define EE 128
#define HH 256
#define NCOL 8
#define NJT 16
#define BT 32
#define WSP 68
#define HSP 260
#define HPAD 264    // bf16 per h-tile row (256 + 8 pad)

typedef unsigned int u32;

// ---------------- device scratch (no allocations allowed) ----------------
__device__ float g_enc_out[BB * SS * HH];   // fp32 encoder hidden states (attention input)
__device__ u32   g_hpack[2][BB * HH];       // packed (bf16 hi | bf16 lo<<16) h, ping-pong
__device__ float g_hfin[BB * HH];           // final process-block h
__device__ float g_M[1024 * 2];             // enc_Wih @ W_emb
__device__ float g_bias[1024];              // enc_bih + enc_bhh
__device__ float g_xp[1024];                // pb_Wih @ dec_input + pb biases
__device__ float g_q[BB * HH];
__device__ float g_u[BB * SS];
__device__ int   g_flag[NCOL * 1024 * NJT]; // per (col, step, slice) done flags

__device__ __forceinline__ float fsig(float x) { return __fdividef(1.f, 1.f + __expf(-x)); }
__device__ __forceinline__ float ftanh(float x) {
    x = fminf(fmaxf(x, -10.f), 10.f);
    float e = __expf(2.f * x);
    return __fdividef(e - 1.f, e + 1.f);
}
__device__ __forceinline__ u32 smem_u32(const void* p) {
    u32 a;
    asm("{ .reg .u64 t; cvta.to.shared.u64 t, %1; cvt.u32.u64 %0, t; }" : "=r"(a) : "l"(p));
    return a;
}
__device__ __forceinline__ void ldsm4(u32& r0, u32& r1, u32& r2, u32& r3, u32 addr) {
    asm volatile("ldmatrix.sync.aligned.m8n8.x4.shared.b16 {%0,%1,%2,%3},[%4];"
                 : "=r"(r0), "=r"(r1), "=r"(r2), "=r"(r3) : "r"(addr));
}
__device__ __forceinline__ void mma16816(float& c0, float& c1, float& c2, float& c3,
                                         u32 a0, u32 a1, u32 a2, u32 a3, u32 b0, u32 b1) {
    asm volatile("mma.sync.aligned.m16n8k16.row.col.f32.bf16.bf16.f32 "
                 "{%0,%1,%2,%3},{%4,%5,%6,%7},{%8,%9},{%0,%1,%2,%3};"
                 : "+f"(c0), "+f"(c1), "+f"(c2), "+f"(c3)
                 : "r"(a0), "r"(a1), "r"(a2), "r"(a3), "r"(b0), "r"(b1));
}
__device__ __forceinline__ u32 pack_hilo(float x, float y, bool lo) {
    __nv_bfloat16 xh = __float2bfloat16(x);
    __nv_bfloat16 yh = __float2bfloat16(y);
    if (lo) {
        xh = __float2bfloat16(x - __bfloat162float(xh));
        yh = __float2bfloat16(y - __bfloat162float(yh));
    }
    return (u32)__bfloat16_as_ushort(xh) | ((u32)__bfloat16_as_ushort(yh) << 16);
}

// ---------------- init: fold small matrices, zero flags ----------------
__global__ void init_kernel(const float* __restrict__ encWih, const float* __restrict__ Wemb,
                            const float* __restrict__ encBih, const float* __restrict__ encBhh,
                            const float* __restrict__ pbWih,  const float* __restrict__ decIn,
                            const float* __restrict__ pbBih,  const float* __restrict__ pbBhh)
{
    int r = blockIdx.x * blockDim.x + threadIdx.x;
    if (r >= 1024) return;
    float m0 = 0.f, m1 = 0.f, xp = 0.f;
    for (int e = 0; e < EE; e++) {
        float w = encWih[r * EE + e];
        m0 = fmaf(w, Wemb[e * 2 + 0], m0);
        m1 = fmaf(w, Wemb[e * 2 + 1], m1);
        xp = fmaf(pbWih[r * EE + e], decIn[e], xp);
    }
    g_M[2 * r] = m0; g_M[2 * r + 1] = m1;
    g_bias[r] = encBih[r] + encBhh[r];
    g_xp[r]   = xp + pbBih[r] + pbBhh[r];
#pragma unroll
    for (int q = 0; q < 128; q++) g_flag[r * 128 + q] = 0;
}

// B fragments (weights, col-major k16n8) for warp w's 8 gate-rows, all 16 k-steps, hi+lo
__device__ __forceinline__ void load_B(const float* __restrict__ W, int j0, int w, int lane,
                                       u32 (&bhi)[16][2], u32 (&blo)[16][2])
{
    int grow = (w >> 1) * HH + j0 + (w & 1) * 8 + (lane >> 2);
    const float* wr = W + (size_t)grow * HH;
    int kc = (lane & 3) * 2;
#pragma unroll
    for (int ks = 0; ks < 16; ks++) {
#pragma unroll
        for (int half = 0; half < 2; half++) {
            float2 v = __ldg((const float2*)(wr + ks * 16 + half * 8 + kc));
            bhi[ks][half] = pack_hilo(v.x, v.y, false);
            blo[ks][half] = pack_hilo(v.x, v.y, true);
        }
    }
}

// ---------------- persistent LSTM: mma.sync bf16 hi/lo recurrence ----------------
__global__ void __launch_bounds__(256)
lstm_kernel(const float* __restrict__ inp,
            const float* __restrict__ encWhh,
            const float* __restrict__ pbWhh)
{
    __shared__ __align__(16) __nv_bfloat16 s_hi[32][HPAD];
    __shared__ __align__(16) __nv_bfloat16 s_lo[32][HPAD];
    __shared__ __align__(16) float s_stg[32][68];

    const int tid  = threadIdx.x;
    const int lane = tid & 31;
    const int w    = tid >> 5;
    const int col  = blockIdx.x & 7;
    const int slc  = blockIdx.x >> 3;
    const int b0g  = col * BT;
    const int j0   = slc * 16;

    // zero h tiles (step 0 mma reads zeros -> gates = bias + x)
#pragma unroll
    for (int i = 0; i < 16; i++) {
        int idx = tid + i * 256;                 // 4096 u32 pair slots
        int b = idx >> 7, kp = idx & 127;
        *(u32*)&s_hi[b][2 * kp] = 0u;
        *(u32*)&s_lo[b][2 * kp] = 0u;
    }

    // constant weight fragments (encoder phase)
    u32 bhi[16][2], blo[16][2];
    load_B(encWhh, j0, w, lane, bhi, blo);

    // per-thread cell constants: jg = tid&15 hidden dim, 2 batches bb, bb+1
    const int jg = tid & 15;
    const int bb = (tid >> 4) * 2;
    float cex[4], cey[4], ceb[4], cxp[4];
#pragma unroll
    for (int m = 0; m < 4; m++) {
        int grow = m * HH + j0 + jg;
        cex[m] = g_M[2 * grow]; cey[m] = g_M[2 * grow + 1];
        ceb[m] = g_bias[grow];  cxp[m] = g_xp[grow];
    }
    float c0 = 0.f, c1 = 0.f;

    // ldmatrix base addrs: row = mt*16 + (lane&15), k-off = (lane>>4)*8
    const int arow = lane & 15;
    const int koff = (lane >> 4) * 8;
    u32 ah[2], al[2];
#pragma unroll
    for (int mt = 0; mt < 2; mt++) {
        ah[mt] = smem_u32(&s_hi[mt * 16 + arow][koff]);
        al[mt] = smem_u32(&s_lo[mt * 16 + arow][koff]);
    }
    __syncthreads();

    for (int step = 0; step < 1024; step++) {
        const bool enc = step < 512;
        if (step == 512) load_B(pbWhh, j0, w, lane, bhi, blo);

        if (step >= 1) {
            if (tid == 0) {
                const int* fb = g_flag + (size_t)((col << 10) + (step - 1)) * NJT;
                for (;;) {
                    int a0, a1, a2, a3, e0, e1, e2, e3;
                    int f0, f1, f2, f3, h0, h1, h2, h3;
                    asm volatile("ld.acquire.gpu.global.v4.b32 {%0,%1,%2,%3},[%4];"
                                 : "=r"(a0), "=r"(a1), "=r"(a2), "=r"(a3) : "l"(fb) : "memory");
                    asm volatile("ld.acquire.gpu.global.v4.b32 {%0,%1,%2,%3},[%4];"
                                 : "=r"(e0), "=r"(e1), "=r"(e2), "=r"(e3) : "l"(fb + 4) : "memory");
                    asm volatile("ld.acquire.gpu.global.v4.b32 {%0,%1,%2,%3},[%4];"
                                 : "=r"(f0), "=r"(f1), "=r"(f2), "=r"(f3) : "l"(fb + 8) : "memory");
                    asm volatile("ld.acquire.gpu.global.v4.b32 {%0,%1,%2,%3},[%4];"
                                 : "=r"(h0), "=r"(h1), "=r"(h2), "=r"(h3) : "l"(fb + 12) : "memory");
                    if ((a0 & a1 & a2 & a3 & e0 & e1 & e2 & e3 &
                         f0 & f1 & f2 & f3 & h0 & h1 & h2 & h3) != 0) break;
                    __nanosleep(20);
                }
            }
            __syncthreads();
            // fill h tiles from packed global h of step-1
            const u32* hp = g_hpack[(step - 1) & 1];
#pragma unroll
            for (int i = 0; i < 16; i++) {
                int idx = tid + i * 256;
                int b = idx >> 7, kp = idx & 127;
                uint2 u = __ldcg((const uint2*)(hp + (size_t)(b0g + b) * HH + 2 * kp));
                *(u32*)&s_hi[b][2 * kp] = (u.x & 0xFFFFu) | (u.y << 16);
                *(u32*)&s_lo[b][2 * kp] = (u.x >> 16) | (u.y & 0xFFFF0000u);
            }
        }
        __syncthreads();

        // tensor-core GEMM: C[32 batch x 64 gate-rows]; warp w owns n-cols [8w, 8w+8)
        float C0[4] = {0.f, 0.f, 0.f, 0.f};   // m-tile 0 (batches 0-15)
        float C1[4] = {0.f, 0.f, 0.f, 0.f};   // m-tile 1 (batches 16-31)
#pragma unroll
        for (int ks = 0; ks < 16; ks++) {
            u32 h0a, h0b, h0c, h0d, l0a, l0b, l0c, l0d;
            u32 h1a, h1b, h1c, h1d, l1a, l1b, l1c, l1d;
            ldsm4(h0a, h0b, h0c, h0d, ah[0] + ks * 32);
            ldsm4(l0a, l0b, l0c, l0d, al[0] + ks * 32);
            ldsm4(h1a, h1b, h1c, h1d, ah[1] + ks * 32);
            ldsm4(l1a, l1b, l1c, l1d, al[1] + ks * 32);
            mma16816(C0[0], C0[1], C0[2], C0[3], h0a, h0b, h0c, h0d, bhi[ks][0], bhi[ks][1]);
            mma16816(C0[0], C0[1], C0[2], C0[3], l0a, l0b, l0c, l0d, bhi[ks][0], bhi[ks][1]);
            mma16816(C0[0], C0[1], C0[2], C0[3], h0a, h0b, h0c, h0d, blo[ks][0], blo[ks][1]);
            mma16816(C1[0], C1[1], C1[2], C1[3], h1a, h1b, h1c, h1d, bhi[ks][0], bhi[ks][1]);
            mma16816(C1[0], C1[1], C1[2], C1[3], l1a, l1b, l1c, l1d, bhi[ks][0], bhi[ks][1]);
            mma16816(C1[0], C1[1], C1[2], C1[3], h1a, h1b, h1c, h1d, blo[ks][0], blo[ks][1]);
        }
        // write C to staging: row b, col n = 8w + (lane&3)*2
        {
            int n = w * 8 + (lane & 3) * 2;
            int r = lane >> 2;
            *(float2*)&s_stg[r][n]      = make_float2(C0[0], C0[1]);
            *(float2*)&s_stg[r + 8][n]  = make_float2(C0[2], C0[3]);
            *(float2*)&s_stg[r + 16][n] = make_float2(C1[0], C1[1]);
            *(float2*)&s_stg[r + 24][n] = make_float2(C1[2], C1[3]);
        }
        __syncthreads();

        // elementwise cell: 2 (jg, b) pairs per thread
        float hout[2];
#pragma unroll
        for (int q = 0; q < 2; q++) {
            int b = bb + q;
            float gi = s_stg[b][jg];
            float gf = s_stg[b][16 + jg];
            float gg = s_stg[b][32 + jg];
            float go = s_stg[b][48 + jg];
            if (enc) {
                float2 x = __ldg((const float2*)(inp + ((size_t)(b0g + b) * SS + step) * 2));
                gi += fmaf(cex[0], x.x, fmaf(cey[0], x.y, ceb[0]));
                gf += fmaf(cex[1], x.x, fmaf(cey[1], x.y, ceb[1]));
                gg += fmaf(cex[2], x.x, fmaf(cey[2], x.y, ceb[2]));
                go += fmaf(cex[3], x.x, fmaf(cey[3], x.y, ceb[3]));
            } else {
                gi += cxp[0]; gf += cxp[1]; gg += cxp[2]; go += cxp[3];
            }
            float& cc = q ? c1 : c0;
            cc = fsig(gf) * cc + fsig(gi) * ftanh(gg);
            float h = fsig(go) * ftanh(cc);
            hout[q] = h;

            if (enc)
                g_enc_out[((size_t)(b0g + b) * SS + step) * HH + j0 + jg] = h;
            if (step == 1023)
                g_hfin[(size_t)(b0g + b) * HH + j0 + jg] = h;
        }
#pragma unroll
        for (int q = 0; q < 2; q++) {
            int b = bb + q;
            float h = hout[q];
            __nv_bfloat16 hh = __float2bfloat16(h);
            float lo = h - __bfloat162float(hh);
            g_hpack[step & 1][(size_t)(b0g + b) * HH + j0 + jg] =
                (u32)__bfloat16_as_ushort(hh) |
                ((u32)__bfloat16_as_ushort(__float2bfloat16(lo)) << 16);
        }
        __syncthreads();
        if (tid == 0) {
            __threadfence();
            asm volatile("st.release.gpu.global.b32 [%0], %1;"
                         :: "l"(g_flag + (size_t)((col << 10) + step) * NJT + slc), "r"(1)
                         : "memory");
        }
    }
}

// ---------------- q = h_final @ Wq^T + bq ----------------
__global__ void qproj_kernel(const float* __restrict__ Wq, const float* __restrict__ bq)
{
    __shared__ float hb[HH];
    int b = blockIdx.x, jx = threadIdx.x;
    hb[jx] = g_hfin[(size_t)b * HH + jx];
    __syncthreads();
    float a = bq[jx];
    const float* wv = Wq + (size_t)jx * HH;
#pragma unroll 8
    for (int k = 0; k < HH; k++) a = fmaf(hb[k], wv[k], a);
    g_q[(size_t)b * HH + jx] = a;
}

// ---------------- attention u (round-6 proven scalar version) ----------------
__device__ __forceinline__ void load_wrows(float* ws, const float* __restrict__ W, int j0, int tid)
{
    int r = tid >> 2;
    int ks = (tid & 3) << 6;
    const float4* src = (const float4*)(W + (size_t)(j0 + r) * HH + ks);
#pragma unroll
    for (int q = 0; q < 16; q++) {
        float4 v = src[q];
        int k = ks + q * 4;
        ws[(k + 0) * WSP + r] = v.x;
        ws[(k + 1) * WSP + r] = v.y;
        ws[(k + 2) * WSP + r] = v.z;
        ws[(k + 3) * WSP + r] = v.w;
    }
}

__global__ void __launch_bounds__(256, 2)
attnU_kernel(const float* __restrict__ Wref, const float* __restrict__ bref,
             const float* __restrict__ V)
{
    extern __shared__ float sm[];
    float* wt = sm;
    float* es = wt + 256 * WSP;
    float* us = es + 32 * HSP;

    const int tid = threadIdx.x;
    const int b  = blockIdx.y;
    const int s0 = blockIdx.x * 32;
    const int jg = tid & 15;
    const int bg = tid >> 4;
    const int r0 = jg * 4;
    const int sn = bg * 2;

#pragma unroll
    for (int it = 0; it < 8; it++) {
        int i = tid + it * 256;
        int s = i >> 6;
        int kq = (i & 63) << 2;
        float4 v = __ldcg((const float4*)(g_enc_out + ((size_t)b * SS + s0 + s) * HH + kq));
        *(float4*)(es + s * HSP + kq) = v;
    }

    float u0 = 0.f, u1 = 0.f;
    for (int jt = 0; jt < 4; jt++) {
        __syncthreads();
        load_wrows(wt, Wref, jt * 64, tid);
        __syncthreads();

        float acc0[4] = {0.f, 0.f, 0.f, 0.f};
        float acc1[4] = {0.f, 0.f, 0.f, 0.f};
        const float* hp0 = es + sn * HSP;
        const float* hp1 = hp0 + HSP;
        const float* wp  = wt + r0;
#pragma unroll 8
        for (int k = 0; k < HH; k += 4) {
            float4 h04 = *(const float4*)(hp0 + k);
            float4 h14 = *(const float4*)(hp1 + k);
            float h0a[4] = {h04.x, h04.y, h04.z, h04.w};
            float h1a[4] = {h14.x, h14.y, h14.z, h14.w};
#pragma unroll
            for (int kk = 0; kk < 4; kk++) {
                float4 w4 = *(const float4*)(wp + (k + kk) * WSP);
                float wa[4] = {w4.x, w4.y, w4.z, w4.w};
#pragma unroll
                for (int jj = 0; jj < 4; jj++) {
                    acc0[jj] = fmaf(h0a[kk], wa[jj], acc0[jj]);
                    acc1[jj] = fmaf(h1a[kk], wa[jj], acc1[jj]);
                }
            }
        }
#pragma unroll
        for (int m = 0; m < 4; m++) {
            int jx = jt * 64 + r0 + m;
            float addv = __ldg(bref + jx) + g_q[(size_t)b * HH + jx];
            float vv = __ldg(V + jx);
            u0 += ftanh(acc0[m] + addv) * vv;
            u1 += ftanh(acc1[m] + addv) * vv;
        }
    }
    us[sn * 17 + jg]       = u0;
    us[(sn + 1) * 17 + jg] = u1;
    __syncthreads();
    if (tid < 32) {
        float t = 0.f;
#pragma unroll
        for (int q = 0; q < 16; q++) t += us[tid * 17 + q];
        g_u[(size_t)b * SS + s0 + tid] = t;
    }
}

// ---------------- softmax + glimpse + head ----------------
__global__ void final_kernel(const float* __restrict__ Wd1, const float* __restrict__ Wd2,
                             float* __restrict__ out)
{
    __shared__ float al[SS];
    __shared__ float red[8];
    __shared__ float gb[HH];
    int b = blockIdx.x, tid = threadIdx.x;
    int lane = tid & 31, wid = tid >> 5;

    float u0 = g_u[(size_t)b * SS + tid];
    float u1 = g_u[(size_t)b * SS + 256 + tid];

    float m = fmaxf(u0, u1);
#pragma unroll
    for (int o = 16; o > 0; o >>= 1) m = fmaxf(m, __shfl_xor_sync(0xffffffffu, m, o));
    if (lane == 0) red[wid] = m;
    __syncthreads();
    float M2 = red[0];
#pragma unroll
    for (int w = 1; w < 8; w++) M2 = fmaxf(M2, red[w]);
    __syncthreads();

    float e0 = __expf(u0 - M2), e1 = __expf(u1 - M2);
    al[tid] = e0; al[tid + 256] = e1;
    float s = e0 + e1;
#pragma unroll
    for (int o = 16; o > 0; o >>= 1) s += __shfl_xor_sync(0xffffffffu, s, o);
    if (lane == 0) red[wid] = s;
    __syncthreads();
    float Ssum = 0.f;
#pragma unroll
    for (int w = 0; w < 8; w++) Ssum += red[w];
    __syncthreads();

    float a0 = 0.f, a1 = 0.f, a2 = 0.f, a3 = 0.f;
    const float* ep = g_enc_out + (size_t)b * SS * HH + tid;
    for (int sIdx = 0; sIdx < SS; sIdx += 4) {
        a0 = fmaf(al[sIdx + 0], __ldcg(ep + (size_t)(sIdx + 0) * HH), a0);
        a1 = fmaf(al[sIdx + 1], __ldcg(ep + (size_t)(sIdx + 1) * HH), a1);
        a2 = fmaf(al[sIdx + 2], __ldcg(ep + (size_t)(sIdx + 2) * HH), a2);
        a3 = fmaf(al[sIdx + 3], __ldcg(ep + (size_t)(sIdx + 3) * HH), a3);
    }
    gb[tid] = ((a0 + a1) + (a2 + a3)) / Ssum;
    __syncthreads();

    float t = 0.f;
    const float* w1 = Wd1 + (size_t)tid * HH;
#pragma unroll 8
    for (int k = 0; k < HH; k++) t = fmaf(gb[k], w1[k], t);
    t = fmaxf(t, 0.f) * __ldg(Wd2 + tid);
#pragma unroll
    for (int o = 16; o > 0; o >>= 1) t += __shfl_xor_sync(0xffffffffu, t, o);
    if (lane == 0) red[wid] = t;
    __syncthreads();
    if (tid == 0) {
        float r = 0.f;
#pragma unroll
        for (int w = 0; w < 8; w++) r += red[w];
        out[b] = r;
    }
}

extern "C" void kernel_launch(void* const* d_in, const int* in_sizes, int n_in,
                              void* d_out, int out_size)
{
    const float* inp    = (const float*)d_in[0];
    const float* Wemb   = (const float*)d_in[1];
    const float* decIn  = (const float*)d_in[2];
    const float* encWih = (const float*)d_in[3];
    const float* encWhh = (const float*)d_in[4];
    const float* encBih = (const float*)d_in[5];
    const float* encBhh = (const float*)d_in[6];
    const float* pbWih  = (const float*)d_in[7];
    const float* pbWhh  = (const float*)d_in[8];
    const float* pbBih  = (const float*)d_in[9];
    const float* pbBhh  = (const float*)d_in[10];
    const float* Wq     = (const float*)d_in[11];
    const float* bq     = (const float*)d_in[12];
    const float* Wref   = (const float*)d_in[13];
    const float* bref   = (const float*)d_in[14];
    const float* V      = (const float*)d_in[15];
    const float* Wd1    = (const float*)d_in[16];
    const float* Wd2    = (const float*)d_in[17];

    const int ATTN_SMEM = (256 * WSP + 32 * HSP + 32 * 17) * 4;
    cudaFuncSetAttribute(attnU_kernel, cudaFuncAttributeMaxDynamicSharedMemorySize, ATTN_SMEM);

    init_kernel<<<4, 256>>>(encWih, Wemb, encBih, encBhh, pbWih, decIn, pbBih, pbBhh);
    lstm_kernel<<<NCOL * NJT, 256>>>(inp, encWhh, pbWhh);
    qproj_kernel<<<BB, 256>>>(Wq, bq);
    attnU_kernel<<<dim3(SS / 32, BB), 256, ATTN_SMEM>>>(Wref, bref, V);
    final_kernel<<<BB, 256>>>(Wd1, Wd2, (float*)d_out);
}